// round 1
// baseline (speedup 1.0000x reference)
#include <cuda_runtime.h>

// KANN_31379031064675 — 2-layer LagrangeKANN (N_WIDTH=64, N_ORDER=3, N_ELEMENTS=64,
// N_NODES=193, P=4, N_SAMPLES=131072, X_MIN=0, X_MAX=1).
//
// Strategy:
//  * Expand weights into SMEM with Lagrange constants folded in:
//      T1[e][j][pair(k,k+32)] as float2  (conflict-free LDS.64, stride 8B)
//      T2[e][k][4] as float4             (conflict-free LDS.128: e-stride = 32 banks,
//                                         k=lane spreads bank groups perfectly)
//  * Warp-per-sample: coalesced x load, shfl broadcast, lane owns widths (lane, lane+32),
//    butterfly reduction over 64 widths, lane-select for coalesced output store.

#define FULL_MASK 0xffffffffu

__global__ void __launch_bounds__(896, 1) kann_kernel(
    const float* __restrict__ x,
    const float* __restrict__ w_inner,
    const float* __restrict__ w_outer,
    float* __restrict__ out, int n)
{
    extern __shared__ float smem[];
    float* T1 = smem;           // 16384 floats: index = e*256 + j*64 + lane*2 + half
    float* T2 = smem + 16384;   // 16384 floats: index = e*256 + k*4 + j

    const int tid = threadIdx.x;

    // ---- build expanded, pre-scaled weight tables ----
    // c_j = 1/prod_{m!=j}(x_j - x_m) for nodes {-1,-1/3,1/3,1}:
    //   c0=-9/16, c1=27/16, c2=-27/16, c3=9/16
    for (int f = tid; f < 16384; f += blockDim.x) {
        int h = f & 1;
        int l = (f >> 1) & 31;
        int j = (f >> 6) & 3;
        int e = f >> 8;
        int k = l + (h << 5);
        float mag = (j == 1 || j == 2) ? 1.6875f : 0.5625f;
        float cj = (j & 1) ? mag : -mag;
        T1[f] = w_inner[k * 193 + 3 * e + j] * cj;
    }
    for (int f = tid; f < 16384; f += blockDim.x) {
        int j = f & 3;
        int k = (f >> 2) & 63;
        int e = f >> 8;
        float mag = (j == 1 || j == 2) ? 1.6875f : 0.5625f;
        float cj = (j & 1) ? mag : -mag;
        T2[f] = w_outer[k * 193 + 3 * e + j] * cj;
    }
    __syncthreads();

    const float2* __restrict__ T1v = (const float2*)T1;  // index e*128 + j*32 + lane
    const float4* __restrict__ T2v = (const float4*)T2;  // index e*64 + k

    const int lane = tid & 31;
    const int wid = tid >> 5;
    const int gwarp = blockIdx.x * (blockDim.x >> 5) + wid;
    const int nwarp = gridDim.x * (blockDim.x >> 5);
    const int ngroups = n >> 5;  // 4096 groups of 32 samples

    for (int g = gwarp; g < ngroups; g += nwarp) {
        const int base = g << 5;
        const float xv = x[base + lane];
        float result = 0.0f;

        #pragma unroll 1
        for (int t = 0; t < 32; ++t) {
            const float x0 = __shfl_sync(FULL_MASK, xv, t);

            // ---------- layer 1 (shared basis per sample) ----------
            float xs = 192.0f * x0;
            float ef = floorf(xs * (1.0f / 3.0f));
            ef = fminf(fmaxf(ef, 0.0f), 63.0f);
            int e1 = (int)ef;
            // xt = (xs - 3*ef - 1.5) / 1.5  ==  (2/3)*xs - 2*ef - 1
            float xt = fmaf(xs, (2.0f / 3.0f), fmaf(ef, -2.0f, -1.0f));
            float p = xt + 1.0f;
            float q = xt + (1.0f / 3.0f);
            float r = xt - (1.0f / 3.0f);
            float s = xt - 1.0f;
            float rs = r * s, pq = p * q;
            float ph0 = q * rs, ph1 = p * rs, ph2 = pq * s, ph3 = pq * r;

            int b1 = (e1 << 7) + lane;  // float2 index
            float2 w0 = T1v[b1];
            float2 w1 = T1v[b1 + 32];
            float2 w2 = T1v[b1 + 64];
            float2 w3 = T1v[b1 + 96];
            float tA = fmaf(ph3, w3.x, fmaf(ph2, w2.x, fmaf(ph1, w1.x, ph0 * w0.x)));
            float tB = fmaf(ph3, w3.y, fmaf(ph2, w2.y, fmaf(ph1, w1.y, ph0 * w0.y)));

            // ---------- layer 2, width A = lane ----------
            float xsA = 192.0f * tA;
            float efA = fminf(fmaxf(floorf(xsA * (1.0f / 3.0f)), 0.0f), 63.0f);
            int eA = (int)efA;
            float xtA = fmaf(xsA, (2.0f / 3.0f), fmaf(efA, -2.0f, -1.0f));
            float pA = xtA + 1.0f, qA = xtA + (1.0f / 3.0f);
            float rA = xtA - (1.0f / 3.0f), sA = xtA - 1.0f;
            float rsA = rA * sA, pqA = pA * qA;

            // ---------- layer 2, width B = lane + 32 ----------
            float xsB = 192.0f * tB;
            float efB = fminf(fmaxf(floorf(xsB * (1.0f / 3.0f)), 0.0f), 63.0f);
            int eB = (int)efB;
            float xtB = fmaf(xsB, (2.0f / 3.0f), fmaf(efB, -2.0f, -1.0f));
            float pB = xtB + 1.0f, qB = xtB + (1.0f / 3.0f);
            float rB = xtB - (1.0f / 3.0f), sB = xtB - 1.0f;
            float rsB = rB * sB, pqB = pB * qB;

            float4 wA = T2v[(eA << 6) + lane];
            float4 wB = T2v[(eB << 6) + 32 + lane];

            float t2A = fmaf(pqA * rA, wA.w,
                        fmaf(pqA * sA, wA.z,
                        fmaf(pA * rsA, wA.y, (qA * rsA) * wA.x)));
            float t2B = fmaf(pqB * rB, wB.w,
                        fmaf(pqB * sB, wB.z,
                        fmaf(pB * rsB, wB.y, (qB * rsB) * wB.x)));

            float local = t2A + t2B;

            // butterfly reduce over 64 widths (32 lanes x 2)
            local += __shfl_xor_sync(FULL_MASK, local, 16);
            local += __shfl_xor_sync(FULL_MASK, local, 8);
            local += __shfl_xor_sync(FULL_MASK, local, 4);
            local += __shfl_xor_sync(FULL_MASK, local, 2);
            local += __shfl_xor_sync(FULL_MASK, local, 1);

            if (lane == t) result = local;
        }
        out[base + lane] = result;
    }
}

extern "C" void kernel_launch(void* const* d_in, const int* in_sizes, int n_in,
                              void* d_out, int out_size) {
    const float* x  = (const float*)d_in[0];
    const float* wi = (const float*)d_in[1];
    const float* wo = (const float*)d_in[2];
    float* out = (float*)d_out;
    const int n = in_sizes[0];

    const int smem_bytes = 2 * 16384 * sizeof(float);  // 128 KB
    cudaFuncSetAttribute(kann_kernel, cudaFuncAttributeMaxDynamicSharedMemorySize,
                         smem_bytes);
    kann_kernel<<<148, 896, smem_bytes>>>(x, wi, wo, out, n);
}